// round 7
// baseline (speedup 1.0000x reference)
#include <cuda_runtime.h>

// PatchShuffle: RATIO=0.75, NUM_ROWS=16, NUM_COLS=64, T=1024, B=64, C=768, STRIPE_W=48
// Output layout (flat fp32):
//   visible [12,582,912] | fwd [65,536] | bwd [65,536] | stripe_bounds [128]

#define NCOLS    64
#define BATCH    64
#define SW       48
#define NVIS     16
#define ROW_F4   192           // float4 per (t,b) row
#define VIS_ELEMS 12582912LL
#define NWARPS   8192u         // 16384 output rows / 2 rows per warp
#define NBLOCKS  1024u         // NWARPS / 8 warps per block

__device__ __forceinline__ int perm_of(int j, int s) {
    return (j < NVIS) ? ((j < s) ? j : j + SW) : (s + (j - NVIS));
}

__global__ void __launch_bounds__(256, 2)   // allow up to 128 regs/thread
patch_shuffle_fused(const float4* __restrict__ patches,
                    const int*    __restrict__ start_cols,
                    float*        __restrict__ out) {
    const unsigned tid = threadIdx.x;
    const unsigned blk = blockIdx.x;

    // ---- index outputs folded into gather blocks: 128 elems per block ----
    if (tid < 128) {
        unsigned k = blk * 128 + tid;          // covers [0, 131072) exactly
        if (k < 65536) {
            // fwd[t, b]
            int b = k & 63;
            int t = k >> 6;
            int j = t & 63, r = t >> 6;
            int s = __ldg(&start_cols[b]);
            __stcs(&out[VIS_ELEMS + k], (float)(r * NCOLS + perm_of(j, s)));
        } else {
            // bwd[p, b] (closed-form inverse)
            unsigned m = k - 65536;
            int b = m & 63;
            int p = m >> 6;
            int c = p & 63, r = p >> 6;
            int s = __ldg(&start_cols[b]);
            int inv = (c < s) ? c : ((c < s + SW) ? (NVIS + c - s) : (c - SW));
            __stcs(&out[VIS_ELEMS + 65536 + m], (float)(r * NCOLS + inv));
        }
    } else if (blk == 0 && tid < 256) {
        // stripe_bounds: 128 elems, row 0 = start, row 1 = start + SW
        unsigned m = tid - 128;
        int b = m & 63;
        int s = __ldg(&start_cols[b]);
        __stcs(&out[VIS_ELEMS + 131072 + m], (float)((m < 64) ? s : s + SW));
    }

    // ---- gather: each warp moves two output rows (w and w + 8192) ----
    unsigned w = blk * 8 + (tid >> 5);         // [0, 8192)
    int lane = tid & 31;
    int b = w & 63;
    int t0 = w >> 6;                           // [0, 128)
    int j  = t0 & 63;
    int r0 = t0 >> 6;                          // [0, 2)
    int s  = __ldg(&start_cols[b]);
    int src_t0 = r0 * NCOLS + perm_of(j, s);   // row for t0
    int src_t1 = src_t0 + 128;                 // row for t0 + 128 (r0 + 2, same j)

    const float4* sp0 = patches + ((long)src_t0 * BATCH + b) * ROW_F4 + lane;
    const float4* sp1 = patches + ((long)src_t1 * BATCH + b) * ROW_F4 + lane;
    float4* dp0 = (float4*)out + (long)w * ROW_F4 + lane;
    float4* dp1 = (float4*)out + (long)(w + NWARPS) * ROW_F4 + lane;

    // 12 independent loads, front-batched (regs budget allows it now)
    float4 a0 = sp0[0];
    float4 a1 = sp0[32];
    float4 a2 = sp0[64];
    float4 a3 = sp0[96];
    float4 a4 = sp0[128];
    float4 a5 = sp0[160];
    float4 b0 = sp1[0];
    float4 b1 = sp1[32];
    float4 b2 = sp1[64];
    float4 b3 = sp1[96];
    float4 b4 = sp1[128];
    float4 b5 = sp1[160];

    // streaming stores: evict-first so the input stays L2-resident across replays
    __stcs(&dp0[0],   a0);
    __stcs(&dp0[32],  a1);
    __stcs(&dp0[64],  a2);
    __stcs(&dp0[96],  a3);
    __stcs(&dp0[128], a4);
    __stcs(&dp0[160], a5);
    __stcs(&dp1[0],   b0);
    __stcs(&dp1[32],  b1);
    __stcs(&dp1[64],  b2);
    __stcs(&dp1[96],  b3);
    __stcs(&dp1[128], b4);
    __stcs(&dp1[160], b5);
}

extern "C" void kernel_launch(void* const* d_in, const int* in_sizes, int n_in,
                              void* d_out, int out_size) {
    const float4* patches    = (const float4*)d_in[0];
    const int*    start_cols = (const int*)d_in[1];
    float*        out        = (float*)d_out;

    patch_shuffle_fused<<<NBLOCKS, 256>>>(patches, start_cols, out);
}